// round 2
// baseline (speedup 1.0000x reference)
#include <cuda_runtime.h>
#include <math.h>

#define BATCH   64
#define IN_F    512
#define OUT_F   512
#define NDIM    8
#define NBLK    64

// Scratch (no allocations allowed -> __device__ globals)
__device__ float gW[OUT_F * IN_F];              // scaled, masked w   (1 MB)
__device__ float gA[NDIM * NBLK * NBLK];        // gA[d][i][o] = exp(g[d,o,i])

// ---------------------------------------------------------------------------
// K1: per-row weight prep. One block (128 thr) per row r of W.
// ---------------------------------------------------------------------------
__global__ void k_weights(const float* __restrict__ W,
                          const float* __restrict__ diag_w) {
    const int r   = blockIdx.x;
    const int rb  = r >> 6;
    const int lo  = rb << 6;
    const int hi  = lo + 64;
    const int tid = threadIdx.x;

    const float* Wrow = W + r * IN_F;
    float wv[4], wu[4];
    float ss = 0.f;
    #pragma unroll
    for (int j = 0; j < 4; j++) {
        const int c = tid + j * 128;
        const float wval = Wrow[c];
        wv[j] = wval;
        float u;
        if (c >= hi)      u = 0.f;
        else if (c >= lo) u = __expf(wval);
        else              u = wval;
        wu[j] = u;
        ss += u * u;
    }
    #pragma unroll
    for (int off = 16; off > 0; off >>= 1)
        ss += __shfl_down_sync(0xffffffffu, ss, off);
    __shared__ float sred[4];
    __shared__ float sbc[2];
    if ((tid & 31) == 0) sred[tid >> 5] = ss;
    __syncthreads();
    if (tid == 0) {
        const float wsn = sred[0] + sred[1] + sred[2] + sred[3];
        const float dv  = diag_w[r];
        sbc[0] = __expf(dv) * rsqrtf(wsn);
        sbc[1] = dv - 0.5f * __logf(wsn);
    }
    __syncthreads();
    const float scale = sbc[0];
    const float c1    = sbc[1];
    #pragma unroll
    for (int j = 0; j < 4; j++) {
        const int c = tid + j * 128;
        gW[r * IN_F + c] = scale * wu[j];
        if (c >= lo && c < hi) {
            const int i = c - lo;
            gA[(rb * 64 + i) * 64 + (r - lo)] = __expf(c1 + wv[j]);   // [d][i][o]
        }
    }
}

// ---------------------------------------------------------------------------
// K2 fused: bid < 64  -> out tile (8b x 64r, full K=512, bias inline)
//           bid >= 64 -> jac for (b,d) pair jbid = bid-64, f32x2 packed GEMM
// ---------------------------------------------------------------------------
__global__ void __launch_bounds__(256) k_main(
        const float* __restrict__ grad,
        const float* __restrict__ inputs,
        const float* __restrict__ bias,
        float* __restrict__ outp) {
    __shared__ float smemBuf[8192];      // jac: As(4096)+Bs(4096); out: sW+sIn
    const int bid = blockIdx.x;
    const int tid = threadIdx.x;

    if (bid < 64) {
        // ------------------- out = inputs @ w^T + bias -------------------
        float* sW  = smemBuf;            // [64][65] padded
        float* sIn = smemBuf + 64 * 65;  // [8][64]
        const int rt = bid >> 3;         // 0..7 : out-col tile (r block)
        const int bt = bid & 7;          // 0..7 : batch tile (8 rows)
        const int b  = tid >> 5;         // 0..7
        const int r2 = (tid & 31) * 2;   // 0,2,..,62
        float acc0 = 0.f, acc1 = 0.f;

        for (int kc = 0; kc < 8; kc++) {
            #pragma unroll
            for (int idx = tid; idx < 4096; idx += 256) {
                const int row = idx >> 6, col = idx & 63;
                sW[row * 65 + col] = gW[(rt * 64 + row) * IN_F + kc * 64 + col];
            }
            if (tid < 512 - 256 || true) {
                for (int idx = tid; idx < 512; idx += 256) {
                    const int row = idx >> 6, col = idx & 63;
                    sIn[row * 64 + col] = inputs[(bt * 8 + row) * IN_F + kc * 64 + col];
                }
            }
            __syncthreads();
            #pragma unroll 8
            for (int kk = 0; kk < 64; kk++) {
                const float iv = sIn[b * 64 + kk];
                acc0 += iv * sW[r2 * 65 + kk];
                acc1 += iv * sW[(r2 + 1) * 65 + kk];
            }
            __syncthreads();
        }
        const int r = rt * 64 + r2;
        float* orow = outp + (bt * 8 + b) * OUT_F + r;
        orow[0] = acc0 + bias[r];
        orow[1] = acc1 + bias[r + 1];
    } else {
        // ------------------- jac: C = gA^T[d] @ exp(grad), log -----------
        const int jbid = bid - 64;       // = b*8 + d
        const int d    = jbid & 7;
        float* As = smemBuf;             // [i][o]
        float* Bs = smemBuf + 4096;      // [i][k]

        const float4* a4 = (const float4*)(gA + d * 4096);
        const float4* g4 = (const float4*)(grad + jbid * 4096);
        float4* As4 = (float4*)As;
        float4* Bs4 = (float4*)Bs;
        #pragma unroll
        for (int idx = tid; idx < 1024; idx += 256) {
            As4[idx] = a4[idx];
            const float4 v = g4[idx];
            Bs4[idx] = make_float4(__expf(v.x), __expf(v.y), __expf(v.z), __expf(v.w));
        }
        __syncthreads();

        const int k_t = tid & 15;        // 16 x4 -> 64 k
        const int o_t = tid >> 4;        // 16 x4 -> 64 o
        // acc[oi][kp] : f32x2 pairs over k
        unsigned long long acc[4][2];
        #pragma unroll
        for (int oi = 0; oi < 4; oi++) { acc[oi][0] = 0ull; acc[oi][1] = 0ull; }

        const float* ap = As + o_t * 4;
        const float* bp = Bs + k_t * 4;
        #pragma unroll 4
        for (int ii = 0; ii < 64; ii++) {
            const float4 a = *(const float4*)(ap + ii * 64);        // broadcast
            const ulonglong2 b2 = *(const ulonglong2*)(bp + ii * 64); // k-pairs
            float a_arr[4] = {a.x, a.y, a.z, a.w};
            #pragma unroll
            for (int oi = 0; oi < 4; oi++) {
                unsigned long long aa;
                asm("mov.b64 %0, {%1, %1};" : "=l"(aa) : "f"(a_arr[oi]));
                asm("fma.rn.f32x2 %0, %1, %2, %0;"
                    : "+l"(acc[oi][0]) : "l"(aa), "l"(b2.x));
                asm("fma.rn.f32x2 %0, %1, %2, %0;"
                    : "+l"(acc[oi][1]) : "l"(aa), "l"(b2.y));
            }
        }

        float* jb = outp + 32768 + jbid * 4096;   // jac block [o][k]
        #pragma unroll
        for (int oi = 0; oi < 4; oi++) {
            float v0, v1, v2, v3;
            asm("mov.b64 {%0, %1}, %2;" : "=f"(v0), "=f"(v1) : "l"(acc[oi][0]));
            asm("mov.b64 {%0, %1}, %2;" : "=f"(v2), "=f"(v3) : "l"(acc[oi][1]));
            float4 r = make_float4(__logf(v0), __logf(v1), __logf(v2), __logf(v3));
            *(float4*)(jb + (o_t * 4 + oi) * 64 + k_t * 4) = r;
        }
    }
}

// ---------------------------------------------------------------------------
// inputs: [0] inputs (64x512 f32), [1] grad (64x8x64x64 f32),
//         [2] W (512x512 f32), [3] diag_w (512 f32), [4] bias (512 f32)
// d_out:  out (64x512) followed by jac (64x8x64x64), f32
// ---------------------------------------------------------------------------
extern "C" void kernel_launch(void* const* d_in, const int* in_sizes, int n_in,
                              void* d_out, int out_size) {
    const float* inputs = (const float*)d_in[0];
    const float* grad   = (const float*)d_in[1];
    const float* W      = (const float*)d_in[2];
    const float* diag_w = (const float*)d_in[3];
    const float* bias   = (const float*)d_in[4];
    float* outp = (float*)d_out;

    k_weights<<<512, 128>>>(W, diag_w);
    k_main<<<512 + 64, 256>>>(grad, inputs, bias, outp);
}